// round 7
// baseline (speedup 1.0000x reference)
#include <cuda_runtime.h>
#include <cstdint>
#include <cstddef>

// Problem dims (fixed)
#define HD 1024
#define FD 3584
#define NE 8
#define RD 79
#define RP 96        // padded low-rank dim (multiple of 32)
#define TMAX 8192
#define AMAX (TMAX*2)

// ----------------------------------------------------------------------------
// Scratch (device globals)
// ----------------------------------------------------------------------------
__device__ __align__(16) float g_P1[(size_t)AMAX * RP];
__device__ __align__(16) float g_P3[(size_t)AMAX * RP];
__device__ __align__(16) float g_Q2[(size_t)AMAX * RP];
__device__ __align__(16) float g_gate[(size_t)AMAX * FD];
__device__ __align__(16) float g_up[(size_t)AMAX * FD];
__device__ __align__(16) float g_U1p[(size_t)NE * FD * RP];
__device__ __align__(16) float g_U3p[(size_t)NE * FD * RP];
__device__ __align__(16) float g_U2p[(size_t)NE * HD * RP];

__device__ int   g_counts[NE];
__device__ int   g_offsets[NE + 1];
__device__ int   g_cursor[NE];
__device__ int   g_tok[AMAX];
__device__ float g_w[AMAX];
__device__ int   g_sel[TMAX * 2];
__device__ float g_wt[TMAX * 2];

// ----------------------------------------------------------------------------
// helpers
// ----------------------------------------------------------------------------
__device__ __forceinline__ float cvt_tf32(float x) {
    uint32_t u;
    asm("cvt.rna.tf32.f32 %0, %1;" : "=r"(u) : "f"(x));
    return __uint_as_float(u);
}
__device__ __forceinline__ float4 cvt_tf32_4(float4 v) {
    v.x = cvt_tf32(v.x); v.y = cvt_tf32(v.y);
    v.z = cvt_tf32(v.z); v.w = cvt_tf32(v.w);
    return v;
}

// ----------------------------------------------------------------------------
// small kernels
// ----------------------------------------------------------------------------
__global__ void zero_kernel(float* __restrict__ out, size_t n) {
    size_t i = (size_t)blockIdx.x * blockDim.x + threadIdx.x;
    size_t stride = (size_t)gridDim.x * blockDim.x;
    for (; i < n; i += stride) out[i] = 0.0f;
    if (blockIdx.x == 0 && threadIdx.x < NE) {
        g_counts[threadIdx.x] = 0;
        g_cursor[threadIdx.x] = 0;
    }
}

__global__ void router_kernel(const float* __restrict__ x,
                              const float* __restrict__ gw,
                              float* __restrict__ logits_out) {
    int t = blockIdx.x;
    __shared__ float xs[HD];
    __shared__ float lg[NE];
    int tid = threadIdx.x;
    for (int i = tid; i < HD; i += 256) xs[i] = x[(size_t)t * HD + i];
    __syncthreads();
    int w = tid >> 5, lane = tid & 31;
    if (w < NE) {
        const float* grow = gw + (size_t)w * HD;
        float s = 0.0f;
        for (int k = lane; k < HD; k += 32) s += xs[k] * grow[k];
        #pragma unroll
        for (int o = 16; o > 0; o >>= 1) s += __shfl_xor_sync(0xffffffffu, s, o);
        if (lane == 0) lg[w] = s;
    }
    __syncthreads();
    if (tid == 0) {
        float l[NE], m = -1e30f;
        #pragma unroll
        for (int e = 0; e < NE; e++) {
            l[e] = lg[e];
            logits_out[(size_t)t * NE + e] = l[e];
            if (l[e] > m) m = l[e];
        }
        float p[NE];
        #pragma unroll
        for (int e = 0; e < NE; e++) p[e] = expf(l[e] - m);
        int i0 = 0;
        #pragma unroll
        for (int e = 1; e < NE; e++) if (p[e] > p[i0]) i0 = e;
        int i1 = (i0 == 0) ? 1 : 0;
        #pragma unroll
        for (int e = 0; e < NE; e++) {
            if (e == i0) continue;
            if (p[e] > p[i1]) i1 = e;
        }
        float p0 = p[i0], p1 = p[i1];
        float inv = 1.0f / (p0 + p1);
        g_sel[t * 2 + 0] = i0;  g_wt[t * 2 + 0] = p0 * inv;
        g_sel[t * 2 + 1] = i1;  g_wt[t * 2 + 1] = p1 * inv;
        atomicAdd(&g_counts[i0], 1);
        atomicAdd(&g_counts[i1], 1);
    }
}

__global__ void scan_kernel() {
    int off = 0;
    g_offsets[0] = 0;
    for (int e = 0; e < NE; e++) {
        off += g_counts[e];
        g_offsets[e + 1] = off;
        g_cursor[e] = g_offsets[e];
    }
}

__global__ void scatter_kernel(int T) {
    int t = blockIdx.x * blockDim.x + threadIdx.x;
    if (t >= T) return;
    #pragma unroll
    for (int j = 0; j < 2; j++) {
        int e = g_sel[t * 2 + j];
        int slot = atomicAdd(&g_cursor[e], 1);
        g_tok[slot] = t;
        g_w[slot] = g_wt[t * 2 + j];
    }
}

// rows of RD -> rows of RP, zero-padded (fp32 exact)
__global__ void pad_kernel(const float* __restrict__ src, float* __restrict__ dst, int rows) {
    long i = (long)blockIdx.x * blockDim.x + threadIdx.x;
    long total = (long)rows * RP;
    long stride = (long)gridDim.x * blockDim.x;
    for (; i < total; i += stride) {
        int r = (int)(i / RP), c = (int)(i % RP);
        dst[i] = (c < RD) ? src[(long)r * RD + c] : 0.0f;
    }
}

__global__ void silu_mul_kernel(float* __restrict__ g, const float* __restrict__ u, size_t n) {
    size_t i = (size_t)blockIdx.x * blockDim.x + threadIdx.x;
    size_t stride = (size_t)gridDim.x * blockDim.x;
    for (; i < n; i += stride) {
        float gv = g[i];
        float s = 1.0f / (1.0f + expf(-gv));
        g[i] = gv * s * u[i];
    }
}

// ----------------------------------------------------------------------------
// TF32 mma.sync MoE GEMM — stall-fixed shape.
//   128 x BN x 32 tile, 512 threads = 16 warps (4x4), double-buffered smem,
//   register-staged LDG, cvt-to-tf32 at STS, ONE __syncthreads per k-tile.
//   C[m,n] = sum_{k<K1} A(row_m)[k] * B(e)[n,k]
//   EPI 0: crow[n] = (n<NReal ? acc : 0)   (writes all BN cols)
//   EPI 2: crow[n] += acc
//   EPI 3: atomicAdd(out[tok*HD+n], w[ga]*acc)
// ----------------------------------------------------------------------------
template <int BN, int K1, bool GATHER, int EPI>
__global__ __launch_bounds__(512, 1)
void gemm_hm(const float* __restrict__ A1,
             const float* __restrict__ Bbase, size_t bstr, int nbrows,
             float* __restrict__ C, int ldc, int NReal,
             float* __restrict__ outp) {
    constexpr int BM = 128;
    constexpr int BK = 32;
    constexpr int NKT = K1 / BK;
    constexpr int WN = BN / 4;                 // 4 warp-cols
    constexpr int MT = 2;                      // WM=32 -> 2 m16 frags
    constexpr int NTL = WN / 8;
    constexpr int LDA = BK + 4;                // 36: conflict-free pad
    constexpr int ASZ = BM * LDA;
    constexpr int BSZ = BN * LDA;
    constexpr int BUF = ASZ + BSZ;             // floats per buffer
    constexpr int LA = BM * 8 / 512;           // 2 float4/thread (A)
    constexpr int LB = (BN * 8 + 511) / 512;   // 2 (B, guarded for BN=96)
    static_assert(K1 % BK == 0 && BN % 32 == 0, "shape");

    const int e = blockIdx.z;
    const int base = g_offsets[e];
    const int cnt = g_offsets[e + 1] - base;
    const int m0 = blockIdx.y * BM;
    if (m0 >= cnt) return;
    const int n0 = blockIdx.x * BN;
    const float* B1 = Bbase + (size_t)e * bstr;

    extern __shared__ float sm[];

    const int tid = threadIdx.x;
    const int lane = tid & 31;
    const int wid = tid >> 5;                  // 0..15
    const int wm = wid & 3;
    const int wn = wid >> 2;

    // ---- loader metadata ----
    const float* aptr[LA];
    int arow[LA], akq[LA];
    #pragma unroll
    for (int i = 0; i < LA; i++) {
        int idx = tid + i * 512;
        arow[i] = idx >> 3;
        akq[i] = (idx & 7) * 4;
        int m = m0 + arow[i];
        int ga = base + ((m < cnt) ? m : (cnt - 1));
        long grow = GATHER ? (long)g_tok[ga] : (long)ga;
        aptr[i] = A1 + grow * K1 + akq[i];
    }
    const float* bptr[LB];
    int brow[LB], bkq[LB];
    bool bin[LB];
    #pragma unroll
    for (int i = 0; i < LB; i++) {
        int idx = tid + i * 512;
        bin[i] = (idx < BN * 8);
        int r = bin[i] ? (idx >> 3) : 0;
        brow[i] = r;
        bkq[i] = (idx & 7) * 4;
        int n = n0 + r;
        int nn = (n < nbrows) ? n : 0;
        bptr[i] = B1 + (size_t)nn * K1 + bkq[i];
    }

    float4 ra[LA], rb[LB];
    auto ldg = [&](int kt) {
        const int kb = kt * BK;
        #pragma unroll
        for (int i = 0; i < LA; i++)
            ra[i] = *reinterpret_cast<const float4*>(aptr[i] + kb);
        #pragma unroll
        for (int i = 0; i < LB; i++)
            if (bin[i]) rb[i] = *reinterpret_cast<const float4*>(bptr[i] + kb);
    };
    auto sts = [&](int buf) {
        float* As = sm + buf * BUF;
        float* Bs = As + ASZ;
        #pragma unroll
        for (int i = 0; i < LA; i++)
            *reinterpret_cast<float4*>(As + arow[i] * LDA + akq[i]) = cvt_tf32_4(ra[i]);
        #pragma unroll
        for (int i = 0; i < LB; i++)
            if (bin[i])
                *reinterpret_cast<float4*>(Bs + brow[i] * LDA + bkq[i]) = cvt_tf32_4(rb[i]);
    };

    float acc[MT][NTL][4];
    #pragma unroll
    for (int mt = 0; mt < MT; mt++)
        #pragma unroll
        for (int nt = 0; nt < NTL; nt++)
            #pragma unroll
            for (int j = 0; j < 4; j++) acc[mt][nt][j] = 0.f;

    ldg(0);
    sts(0);
    __syncthreads();

    for (int kt = 0; kt < NKT; kt++) {
        if (kt + 1 < NKT) ldg(kt + 1);         // in flight during compute
        const float* As = sm + (kt & 1) * BUF;
        const float* Bs = As + ASZ;
        #pragma unroll
        for (int ks = 0; ks < BK / 8; ks++) {
            const int k0 = ks * 8 + (lane & 3);
            uint32_t afr[MT][4];
            uint32_t bfr[NTL][2];
            #pragma unroll
            for (int mt = 0; mt < MT; mt++) {
                int m = wm * 32 + mt * 16 + (lane >> 2);
                afr[mt][0] = __float_as_uint(As[m * LDA + k0]);
                afr[mt][1] = __float_as_uint(As[(m + 8) * LDA + k0]);
                afr[mt][2] = __float_as_uint(As[m * LDA + k0 + 4]);
                afr[mt][3] = __float_as_uint(As[(m + 8) * LDA + k0 + 4]);
            }
            #pragma unroll
            for (int nt = 0; nt < NTL; nt++) {
                int n = wn * WN + nt * 8 + (lane >> 2);
                bfr[nt][0] = __float_as_uint(Bs[n * LDA + k0]);
                bfr[nt][1] = __float_as_uint(Bs[n * LDA + k0 + 4]);
            }
            #pragma unroll
            for (int mt = 0; mt < MT; mt++)
                #pragma unroll
                for (int nt = 0; nt < NTL; nt++) {
                    asm volatile(
                        "mma.sync.aligned.m16n8k8.row.col.f32.tf32.tf32.f32 "
                        "{%0,%1,%2,%3}, {%4,%5,%6,%7}, {%8,%9}, {%0,%1,%2,%3};\n"
                        : "+f"(acc[mt][nt][0]), "+f"(acc[mt][nt][1]),
                          "+f"(acc[mt][nt][2]), "+f"(acc[mt][nt][3])
                        : "r"(afr[mt][0]), "r"(afr[mt][1]),
                          "r"(afr[mt][2]), "r"(afr[mt][3]),
                          "r"(bfr[nt][0]), "r"(bfr[nt][1]));
                }
        }
        if (kt + 1 < NKT) {
            sts((kt + 1) & 1);                 // other buffer: no race with compute(kt)
            __syncthreads();
        }
    }

    // ---- epilogue ----
    #pragma unroll
    for (int mt = 0; mt < MT; mt++) {
        #pragma unroll
        for (int h = 0; h < 2; h++) {
            int ml = wm * 32 + mt * 16 + (lane >> 2) + h * 8;
            int m = m0 + ml;
            if (m >= cnt) continue;
            int ga = base + m;
            if (EPI == 0) {
                float* crow = C + (size_t)ga * ldc;
                #pragma unroll
                for (int nt = 0; nt < NTL; nt++) {
                    int col = n0 + wn * WN + nt * 8 + 2 * (lane & 3);
                    float2 v;
                    v.x = (col < NReal) ? acc[mt][nt][h * 2 + 0] : 0.0f;
                    v.y = (col + 1 < NReal) ? acc[mt][nt][h * 2 + 1] : 0.0f;
                    *reinterpret_cast<float2*>(crow + col) = v;
                }
            } else if (EPI == 2) {
                float* crow = C + (size_t)ga * ldc;
                #pragma unroll
                for (int nt = 0; nt < NTL; nt++) {
                    int col = n0 + wn * WN + nt * 8 + 2 * (lane & 3);
                    float2* cp = reinterpret_cast<float2*>(crow + col);
                    float2 v = *cp;
                    v.x += acc[mt][nt][h * 2 + 0];
                    v.y += acc[mt][nt][h * 2 + 1];
                    *cp = v;
                }
            } else {
                int tok = g_tok[ga];
                float wgt = g_w[ga];
                float* orow = outp + (size_t)tok * HD;
                #pragma unroll
                for (int nt = 0; nt < NTL; nt++) {
                    int col = n0 + wn * WN + nt * 8 + 2 * (lane & 3);
                    atomicAdd(&orow[col], wgt * acc[mt][nt][h * 2 + 0]);
                    atomicAdd(&orow[col + 1], wgt * acc[mt][nt][h * 2 + 1]);
                }
            }
        }
    }
}

// ----------------------------------------------------------------------------
// kernel_launch
// Inputs: hidden_states, gate_w, W1, W2, W3, U1, V1, U2, V2, U3, V3
// Output: [out (T*H f32)] then [router_logits (T*E f32)]
// ----------------------------------------------------------------------------
extern "C" void kernel_launch(void* const* d_in, const int* in_sizes, int n_in,
                              void* d_out, int out_size) {
    const float* x  = (const float*)d_in[0];
    const float* gw = (const float*)d_in[1];
    const float* W1 = (const float*)d_in[2];
    const float* W2 = (const float*)d_in[3];
    const float* W3 = (const float*)d_in[4];
    const float* U1 = (const float*)d_in[5];
    const float* V1 = (const float*)d_in[6];
    const float* U2 = (const float*)d_in[7];
    const float* V2 = (const float*)d_in[8];
    const float* U3 = (const float*)d_in[9];
    const float* V3 = (const float*)d_in[10];
    (void)n_in; (void)out_size;

    const int T = in_sizes[0] / HD;
    const int A = T * 2;

    float* out    = (float*)d_out;
    float* logits = out + (size_t)T * HD;

    // instantiations + dynamic smem opt-in
    auto* gP  = gemm_hm< 96, HD, true,  0>;   // P = X@V^T   (N=79 pad 96)
    auto* gM  = gemm_hm<128, HD, true,  0>;   // gate/up main
    auto* gLR = gemm_hm<128, RP, false, 2>;   // += P@U^T
    auto* gQ  = gemm_hm< 96, FD, false, 0>;   // Q2 = H@V2^T
    auto* gD  = gemm_hm<128, FD, false, 3>;   // down main (atomic)
    auto* gDL = gemm_hm<128, RP, false, 3>;   // down lr (atomic)
    const int SM128 = 2 * (128 + 128) * 36 * 4;   // 73,728 B
    const int SM96  = 2 * (128 +  96) * 36 * 4;   // 64,512 B
    cudaFuncSetAttribute((const void*)gP,  cudaFuncAttributeMaxDynamicSharedMemorySize, SM96);
    cudaFuncSetAttribute((const void*)gM,  cudaFuncAttributeMaxDynamicSharedMemorySize, SM128);
    cudaFuncSetAttribute((const void*)gLR, cudaFuncAttributeMaxDynamicSharedMemorySize, SM128);
    cudaFuncSetAttribute((const void*)gQ,  cudaFuncAttributeMaxDynamicSharedMemorySize, SM96);
    cudaFuncSetAttribute((const void*)gD,  cudaFuncAttributeMaxDynamicSharedMemorySize, SM128);
    cudaFuncSetAttribute((const void*)gDL, cudaFuncAttributeMaxDynamicSharedMemorySize, SM128);

    zero_kernel<<<2048, 256>>>(out, (size_t)T * HD);
    router_kernel<<<T, 256>>>(x, gw, logits);
    scan_kernel<<<1, 1>>>();
    scatter_kernel<<<(T + 255) / 256, 256>>>(T);

    // zero-padded low-rank U matrices (fp32, exact)
    pad_kernel<<<2048, 256>>>(U1, g_U1p, NE * FD);
    pad_kernel<<<2048, 256>>>(U3, g_U3p, NE * FD);
    pad_kernel<<<1024, 256>>>(U2, g_U2p, NE * HD);

    const int mt128 = (T + 127) / 128;

    // P1 = X@V1^T, P3 = X@V3^T  (N=79 -> stride 96 zero-padded)
    {
        dim3 grid(1, mt128, NE);
        gP<<<grid, 512, SM96>>>(x, V1, (size_t)RD * HD, RD, g_P1, RP, RD, nullptr);
        gP<<<grid, 512, SM96>>>(x, V3, (size_t)RD * HD, RD, g_P3, RP, RD, nullptr);
    }
    // gate = X@W1^T, up = X@W3^T
    {
        dim3 grid(FD / 128, mt128, NE);
        gM<<<grid, 512, SM128>>>(x, W1, (size_t)FD * HD, FD, g_gate, FD, FD, nullptr);
        gM<<<grid, 512, SM128>>>(x, W3, (size_t)FD * HD, FD, g_up, FD, FD, nullptr);
    }
    // gate += P1@U1p^T, up += P3@U3p^T  (K=96)
    {
        dim3 grid(FD / 128, mt128, NE);
        gLR<<<grid, 512, SM128>>>(g_P1, g_U1p, (size_t)FD * RP, FD, g_gate, FD, FD, nullptr);
        gLR<<<grid, 512, SM128>>>(g_P3, g_U3p, (size_t)FD * RP, FD, g_up, FD, FD, nullptr);
    }
    // Hact = silu(gate)*up
    silu_mul_kernel<<<4096, 256>>>(g_gate, g_up, (size_t)A * FD);

    // Q2 = Hact@V2^T  (K=3584, N=79 -> stride 96)
    {
        dim3 grid(1, mt128, NE);
        gQ<<<grid, 512, SM96>>>(g_gate, V2, (size_t)RD * FD, RD, g_Q2, RP, RD, nullptr);
    }
    // out += w*(Hact@W2^T)  (K=3584, atomic scatter)
    {
        dim3 grid(HD / 128, mt128, NE);
        gD<<<grid, 512, SM128>>>(g_gate, W2, (size_t)HD * FD, HD, nullptr, HD, HD, out);
    }
    // out += w*(Q2@U2p^T)  (K=96, atomic scatter)
    {
        dim3 grid(HD / 128, mt128, NE);
        gDL<<<grid, 512, SM128>>>(g_Q2, g_U2p, (size_t)HD * RP, HD, nullptr, HD, HD, out);
    }
}

// round 8
// speedup vs baseline: 1.0575x; 1.0575x over previous
#include <cuda_runtime.h>
#include <cstdint>
#include <cstddef>

// Problem dims (fixed)
#define HD 1024
#define FD 3584
#define NE 8
#define RD 79
#define RP 96        // padded low-rank dim (multiple of 32)
#define TMAX 8192
#define AMAX (TMAX*2)

// ----------------------------------------------------------------------------
// Scratch (device globals)
// ----------------------------------------------------------------------------
__device__ __align__(16) float g_P1[(size_t)AMAX * RP];
__device__ __align__(16) float g_P3[(size_t)AMAX * RP];
__device__ __align__(16) float g_Q2[(size_t)AMAX * RP];
__device__ __align__(16) float g_gate[(size_t)AMAX * FD];
__device__ __align__(16) float g_up[(size_t)AMAX * FD];
__device__ __align__(16) float g_U1p[(size_t)NE * FD * RP];
__device__ __align__(16) float g_U3p[(size_t)NE * FD * RP];
__device__ __align__(16) float g_U2p[(size_t)NE * HD * RP];

__device__ int   g_counts[NE];
__device__ int   g_offsets[NE + 1];
__device__ int   g_cursor[NE];
__device__ int   g_tok[AMAX];
__device__ float g_w[AMAX];
__device__ int   g_sel[TMAX * 2];
__device__ float g_wt[TMAX * 2];

// ----------------------------------------------------------------------------
// helpers
// ----------------------------------------------------------------------------
__device__ __forceinline__ float cvt_tf32(float x) {
    uint32_t u;
    asm("cvt.rna.tf32.f32 %0, %1;" : "=r"(u) : "f"(x));
    return __uint_as_float(u);
}
__device__ __forceinline__ float4 cvt_tf32_4(float4 v) {
    v.x = cvt_tf32(v.x); v.y = cvt_tf32(v.y);
    v.z = cvt_tf32(v.z); v.w = cvt_tf32(v.w);
    return v;
}

// ----------------------------------------------------------------------------
// small kernels
// ----------------------------------------------------------------------------
__global__ void zero_kernel(float* __restrict__ out, size_t n) {
    size_t i = (size_t)blockIdx.x * blockDim.x + threadIdx.x;
    size_t stride = (size_t)gridDim.x * blockDim.x;
    for (; i < n; i += stride) out[i] = 0.0f;
    if (blockIdx.x == 0 && threadIdx.x < NE) {
        g_counts[threadIdx.x] = 0;
        g_cursor[threadIdx.x] = 0;
    }
}

__global__ void router_kernel(const float* __restrict__ x,
                              const float* __restrict__ gw,
                              float* __restrict__ logits_out) {
    int t = blockIdx.x;
    __shared__ float xs[HD];
    __shared__ float lg[NE];
    int tid = threadIdx.x;
    for (int i = tid; i < HD; i += 256) xs[i] = x[(size_t)t * HD + i];
    __syncthreads();
    int w = tid >> 5, lane = tid & 31;
    if (w < NE) {
        const float* grow = gw + (size_t)w * HD;
        float s = 0.0f;
        for (int k = lane; k < HD; k += 32) s += xs[k] * grow[k];
        #pragma unroll
        for (int o = 16; o > 0; o >>= 1) s += __shfl_xor_sync(0xffffffffu, s, o);
        if (lane == 0) lg[w] = s;
    }
    __syncthreads();
    if (tid == 0) {
        float l[NE], m = -1e30f;
        #pragma unroll
        for (int e = 0; e < NE; e++) {
            l[e] = lg[e];
            logits_out[(size_t)t * NE + e] = l[e];
            if (l[e] > m) m = l[e];
        }
        float p[NE];
        #pragma unroll
        for (int e = 0; e < NE; e++) p[e] = expf(l[e] - m);
        int i0 = 0;
        #pragma unroll
        for (int e = 1; e < NE; e++) if (p[e] > p[i0]) i0 = e;
        int i1 = (i0 == 0) ? 1 : 0;
        #pragma unroll
        for (int e = 0; e < NE; e++) {
            if (e == i0) continue;
            if (p[e] > p[i1]) i1 = e;
        }
        float p0 = p[i0], p1 = p[i1];
        float inv = 1.0f / (p0 + p1);
        g_sel[t * 2 + 0] = i0;  g_wt[t * 2 + 0] = p0 * inv;
        g_sel[t * 2 + 1] = i1;  g_wt[t * 2 + 1] = p1 * inv;
        atomicAdd(&g_counts[i0], 1);
        atomicAdd(&g_counts[i1], 1);
    }
}

__global__ void scan_kernel() {
    int off = 0;
    g_offsets[0] = 0;
    for (int e = 0; e < NE; e++) {
        off += g_counts[e];
        g_offsets[e + 1] = off;
        g_cursor[e] = g_offsets[e];
    }
}

__global__ void scatter_kernel(int T) {
    int t = blockIdx.x * blockDim.x + threadIdx.x;
    if (t >= T) return;
    #pragma unroll
    for (int j = 0; j < 2; j++) {
        int e = g_sel[t * 2 + j];
        int slot = atomicAdd(&g_cursor[e], 1);
        g_tok[slot] = t;
        g_w[slot] = g_wt[t * 2 + j];
    }
}

// rows of RD -> rows of RP, zero-padded (fp32 exact)
__global__ void pad_kernel(const float* __restrict__ src, float* __restrict__ dst, int rows) {
    long i = (long)blockIdx.x * blockDim.x + threadIdx.x;
    long total = (long)rows * RP;
    long stride = (long)gridDim.x * blockDim.x;
    for (; i < total; i += stride) {
        int r = (int)(i / RP), c = (int)(i % RP);
        dst[i] = (c < RD) ? src[(long)r * RD + c] : 0.0f;
    }
}

__global__ void silu_mul_kernel(float* __restrict__ g, const float* __restrict__ u, size_t n) {
    size_t i = (size_t)blockIdx.x * blockDim.x + threadIdx.x;
    size_t stride = (size_t)gridDim.x * blockDim.x;
    for (; i < n; i += stride) {
        float gv = g[i];
        float s = 1.0f / (1.0f + expf(-gv));
        g[i] = gv * s * u[i];
    }
}

// ----------------------------------------------------------------------------
// TF32 mma.sync MoE GEMM — R2 warp geometry + double-buffered smem (1 sync/tile).
//   128 x BN x 32 tile, 256 threads = 8 warps (WARPS_M x WARPS_N),
//   register-staged LDG, cvt-to-tf32 at STS, uniform K (no tail path).
//   C[m,n] = sum_{k<K1} A(row_m)[k] * B(e)[n,k]
//   EPI 0: crow[n] = (n<NReal ? acc : 0)   (writes all BN cols)
//   EPI 2: crow[n] += acc
//   EPI 3: atomicAdd(out[tok*HD+n], w[ga]*acc)
// ----------------------------------------------------------------------------
template <int BN, int WARPS_M, int WARPS_N, int K1, bool GATHER, int EPI>
__global__ __launch_bounds__(256, 1)
void gemm_hm(const float* __restrict__ A1,
             const float* __restrict__ Bbase, size_t bstr, int nbrows,
             float* __restrict__ C, int ldc, int NReal,
             float* __restrict__ outp) {
    constexpr int BM = 128;
    constexpr int BK = 32;
    constexpr int NKT = K1 / BK;
    constexpr int WM = BM / WARPS_M;
    constexpr int WN = BN / WARPS_N;
    constexpr int MT = WM / 16;
    constexpr int NTL = WN / 8;
    constexpr int LDA = BK + 4;                // 36: conflict-free pad
    constexpr int ASZ = BM * LDA;
    constexpr int BSZ = BN * LDA;
    constexpr int BUF = ASZ + BSZ;             // floats per buffer
    constexpr int LA = BM * 8 / 256;           // float4 chunks/thread (A)
    constexpr int LB = (BN * 8 + 255) / 256;   // (B)
    static_assert(BM * 8 % 256 == 0 && K1 % BK == 0, "shape");

    const int e = blockIdx.z;
    const int base = g_offsets[e];
    const int cnt = g_offsets[e + 1] - base;
    const int m0 = blockIdx.y * BM;
    if (m0 >= cnt) return;
    const int n0 = blockIdx.x * BN;
    const float* B1 = Bbase + (size_t)e * bstr;

    extern __shared__ float sm[];

    const int tid = threadIdx.x;
    const int lane = tid & 31;
    const int wid = tid >> 5;
    const int wm = wid % WARPS_M;
    const int wn = wid / WARPS_M;

    // ---- loader metadata ----
    const float* aptr[LA];
    int arow[LA], akq[LA];
    #pragma unroll
    for (int i = 0; i < LA; i++) {
        int idx = tid + i * 256;
        arow[i] = idx >> 3;
        akq[i] = (idx & 7) * 4;
        int m = m0 + arow[i];
        int ga = base + ((m < cnt) ? m : (cnt - 1));
        long grow = GATHER ? (long)g_tok[ga] : (long)ga;
        aptr[i] = A1 + grow * K1 + akq[i];
    }
    const float* bptr[LB];
    int brow[LB], bkq[LB];
    bool bin[LB];
    #pragma unroll
    for (int i = 0; i < LB; i++) {
        int idx = tid + i * 256;
        bin[i] = (idx < BN * 8);
        int r = bin[i] ? (idx >> 3) : 0;
        brow[i] = r;
        bkq[i] = (idx & 7) * 4;
        int n = n0 + r;
        int nn = (n < nbrows) ? n : 0;
        bptr[i] = B1 + (size_t)nn * K1 + bkq[i];
    }

    float4 ra[LA], rb[LB];
    auto ldg = [&](int kt) {
        const int kb = kt * BK;
        #pragma unroll
        for (int i = 0; i < LA; i++)
            ra[i] = *reinterpret_cast<const float4*>(aptr[i] + kb);
        #pragma unroll
        for (int i = 0; i < LB; i++)
            if (bin[i]) rb[i] = *reinterpret_cast<const float4*>(bptr[i] + kb);
    };
    auto sts = [&](int buf) {
        float* As = sm + buf * BUF;
        float* Bs = As + ASZ;
        #pragma unroll
        for (int i = 0; i < LA; i++)
            *reinterpret_cast<float4*>(As + arow[i] * LDA + akq[i]) = cvt_tf32_4(ra[i]);
        #pragma unroll
        for (int i = 0; i < LB; i++)
            if (bin[i])
                *reinterpret_cast<float4*>(Bs + brow[i] * LDA + bkq[i]) = cvt_tf32_4(rb[i]);
    };

    float acc[MT][NTL][4];
    #pragma unroll
    for (int mt = 0; mt < MT; mt++)
        #pragma unroll
        for (int nt = 0; nt < NTL; nt++)
            #pragma unroll
            for (int j = 0; j < 4; j++) acc[mt][nt][j] = 0.f;

    ldg(0);
    sts(0);
    __syncthreads();

    for (int kt = 0; kt < NKT; kt++) {
        if (kt + 1 < NKT) ldg(kt + 1);         // overlaps compute below
        const float* As = sm + (kt & 1) * BUF;
        const float* Bs = As + ASZ;
        #pragma unroll
        for (int ks = 0; ks < BK / 8; ks++) {
            const int k0 = ks * 8 + (lane & 3);
            uint32_t afr[MT][4];
            uint32_t bfr[NTL][2];
            #pragma unroll
            for (int mt = 0; mt < MT; mt++) {
                int m = wm * WM + mt * 16 + (lane >> 2);
                afr[mt][0] = __float_as_uint(As[m * LDA + k0]);
                afr[mt][1] = __float_as_uint(As[(m + 8) * LDA + k0]);
                afr[mt][2] = __float_as_uint(As[m * LDA + k0 + 4]);
                afr[mt][3] = __float_as_uint(As[(m + 8) * LDA + k0 + 4]);
            }
            #pragma unroll
            for (int nt = 0; nt < NTL; nt++) {
                int n = wn * WN + nt * 8 + (lane >> 2);
                bfr[nt][0] = __float_as_uint(Bs[n * LDA + k0]);
                bfr[nt][1] = __float_as_uint(Bs[n * LDA + k0 + 4]);
            }
            #pragma unroll
            for (int mt = 0; mt < MT; mt++)
                #pragma unroll
                for (int nt = 0; nt < NTL; nt++) {
                    asm volatile(
                        "mma.sync.aligned.m16n8k8.row.col.f32.tf32.tf32.f32 "
                        "{%0,%1,%2,%3}, {%4,%5,%6,%7}, {%8,%9}, {%0,%1,%2,%3};\n"
                        : "+f"(acc[mt][nt][0]), "+f"(acc[mt][nt][1]),
                          "+f"(acc[mt][nt][2]), "+f"(acc[mt][nt][3])
                        : "r"(afr[mt][0]), "r"(afr[mt][1]),
                          "r"(afr[mt][2]), "r"(afr[mt][3]),
                          "r"(bfr[nt][0]), "r"(bfr[nt][1]));
                }
        }
        if (kt + 1 < NKT) {
            sts((kt + 1) & 1);                 // other buffer — no race with compute(kt)
            __syncthreads();                   // single barrier per k-tile
        }
    }

    // ---- epilogue ----
    #pragma unroll
    for (int mt = 0; mt < MT; mt++) {
        #pragma unroll
        for (int h = 0; h < 2; h++) {
            int ml = wm * WM + mt * 16 + (lane >> 2) + h * 8;
            int m = m0 + ml;
            if (m >= cnt) continue;
            int ga = base + m;
            if (EPI == 0) {
                float* crow = C + (size_t)ga * ldc;
                #pragma unroll
                for (int nt = 0; nt < NTL; nt++) {
                    int col = n0 + wn * WN + nt * 8 + 2 * (lane & 3);
                    float2 v;
                    v.x = (col < NReal) ? acc[mt][nt][h * 2 + 0] : 0.0f;
                    v.y = (col + 1 < NReal) ? acc[mt][nt][h * 2 + 1] : 0.0f;
                    *reinterpret_cast<float2*>(crow + col) = v;
                }
            } else if (EPI == 2) {
                float* crow = C + (size_t)ga * ldc;
                #pragma unroll
                for (int nt = 0; nt < NTL; nt++) {
                    int col = n0 + wn * WN + nt * 8 + 2 * (lane & 3);
                    float2* cp = reinterpret_cast<float2*>(crow + col);
                    float2 v = *cp;
                    v.x += acc[mt][nt][h * 2 + 0];
                    v.y += acc[mt][nt][h * 2 + 1];
                    *cp = v;
                }
            } else {
                int tok = g_tok[ga];
                float wgt = g_w[ga];
                float* orow = outp + (size_t)tok * HD;
                #pragma unroll
                for (int nt = 0; nt < NTL; nt++) {
                    int col = n0 + wn * WN + nt * 8 + 2 * (lane & 3);
                    atomicAdd(&orow[col], wgt * acc[mt][nt][h * 2 + 0]);
                    atomicAdd(&orow[col + 1], wgt * acc[mt][nt][h * 2 + 1]);
                }
            }
        }
    }
}

// ----------------------------------------------------------------------------
// kernel_launch
// Inputs: hidden_states, gate_w, W1, W2, W3, U1, V1, U2, V2, U3, V3
// Output: [out (T*H f32)] then [router_logits (T*E f32)]
// ----------------------------------------------------------------------------
extern "C" void kernel_launch(void* const* d_in, const int* in_sizes, int n_in,
                              void* d_out, int out_size) {
    const float* x  = (const float*)d_in[0];
    const float* gw = (const float*)d_in[1];
    const float* W1 = (const float*)d_in[2];
    const float* W2 = (const float*)d_in[3];
    const float* W3 = (const float*)d_in[4];
    const float* U1 = (const float*)d_in[5];
    const float* V1 = (const float*)d_in[6];
    const float* U2 = (const float*)d_in[7];
    const float* V2 = (const float*)d_in[8];
    const float* U3 = (const float*)d_in[9];
    const float* V3 = (const float*)d_in[10];
    (void)n_in; (void)out_size;

    const int T = in_sizes[0] / HD;
    const int A = T * 2;

    float* out    = (float*)d_out;
    float* logits = out + (size_t)T * HD;

    // instantiations (R2 warp geometry: 2x4 for BN=128, 4x2 for BN=96)
    auto* gP  = gemm_hm< 96, 4, 2, HD, true,  0>;   // P = X@V^T   (N=79 pad 96)
    auto* gM  = gemm_hm<128, 2, 4, HD, true,  0>;   // gate/up main
    auto* gLR = gemm_hm<128, 2, 4, RP, false, 2>;   // += P@U^T
    auto* gQ  = gemm_hm< 96, 4, 2, FD, false, 0>;   // Q2 = H@V2^T
    auto* gD  = gemm_hm<128, 2, 4, FD, false, 3>;   // down main (atomic)
    auto* gDL = gemm_hm<128, 2, 4, RP, false, 3>;   // down lr (atomic)
    const int SM128 = 2 * (128 + 128) * 36 * 4;   // 73,728 B
    const int SM96  = 2 * (128 +  96) * 36 * 4;   // 64,512 B
    cudaFuncSetAttribute((const void*)gP,  cudaFuncAttributeMaxDynamicSharedMemorySize, SM96);
    cudaFuncSetAttribute((const void*)gM,  cudaFuncAttributeMaxDynamicSharedMemorySize, SM128);
    cudaFuncSetAttribute((const void*)gLR, cudaFuncAttributeMaxDynamicSharedMemorySize, SM128);
    cudaFuncSetAttribute((const void*)gQ,  cudaFuncAttributeMaxDynamicSharedMemorySize, SM96);
    cudaFuncSetAttribute((const void*)gD,  cudaFuncAttributeMaxDynamicSharedMemorySize, SM128);
    cudaFuncSetAttribute((const void*)gDL, cudaFuncAttributeMaxDynamicSharedMemorySize, SM128);

    zero_kernel<<<2048, 256>>>(out, (size_t)T * HD);
    router_kernel<<<T, 256>>>(x, gw, logits);
    scan_kernel<<<1, 1>>>();
    scatter_kernel<<<(T + 255) / 256, 256>>>(T);

    // zero-padded low-rank U matrices (fp32, exact)
    pad_kernel<<<2048, 256>>>(U1, g_U1p, NE * FD);
    pad_kernel<<<2048, 256>>>(U3, g_U3p, NE * FD);
    pad_kernel<<<1024, 256>>>(U2, g_U2p, NE * HD);

    const int mt128 = (T + 127) / 128;

    // P1 = X@V1^T, P3 = X@V3^T  (N=79 -> stride 96 zero-padded)
    {
        dim3 grid(1, mt128, NE);
        gP<<<grid, 256, SM96>>>(x, V1, (size_t)RD * HD, RD, g_P1, RP, RD, nullptr);
        gP<<<grid, 256, SM96>>>(x, V3, (size_t)RD * HD, RD, g_P3, RP, RD, nullptr);
    }
    // gate = X@W1^T, up = X@W3^T
    {
        dim3 grid(FD / 128, mt128, NE);
        gM<<<grid, 256, SM128>>>(x, W1, (size_t)FD * HD, FD, g_gate, FD, FD, nullptr);
        gM<<<grid, 256, SM128>>>(x, W3, (size_t)FD * HD, FD, g_up, FD, FD, nullptr);
    }
    // gate += P1@U1p^T, up += P3@U3p^T  (K=96)
    {
        dim3 grid(FD / 128, mt128, NE);
        gLR<<<grid, 256, SM128>>>(g_P1, g_U1p, (size_t)FD * RP, FD, g_gate, FD, FD, nullptr);
        gLR<<<grid, 256, SM128>>>(g_P3, g_U3p, (size_t)FD * RP, FD, g_up, FD, FD, nullptr);
    }
    // Hact = silu(gate)*up
    silu_mul_kernel<<<4096, 256>>>(g_gate, g_up, (size_t)A * FD);

    // Q2 = Hact@V2^T  (K=3584, N=79 -> stride 96)
    {
        dim3 grid(1, mt128, NE);
        gQ<<<grid, 256, SM96>>>(g_gate, V2, (size_t)RD * FD, RD, g_Q2, RP, RD, nullptr);
    }
    // out += w*(Hact@W2^T)  (K=3584, atomic scatter)
    {
        dim3 grid(HD / 128, mt128, NE);
        gD<<<grid, 256, SM128>>>(g_gate, W2, (size_t)HD * FD, HD, nullptr, HD, HD, out);
    }
    // out += w*(Q2@U2p^T)  (K=96, atomic scatter)
    {
        dim3 grid(HD / 128, mt128, NE);
        gDL<<<grid, 256, SM128>>>(g_Q2, g_U2p, (size_t)HD * RP, HD, nullptr, HD, HD, out);
    }
}

// round 9
// speedup vs baseline: 1.5211x; 1.4384x over previous
#include <cuda_runtime.h>
#include <cstdint>
#include <cstddef>

// Problem dims (fixed)
#define HD 1024
#define FD 3584
#define NE 8
#define RD 79
#define RP 96        // padded low-rank dim (multiple of 32)
#define TMAX 8192
#define AMAX (TMAX*2)

// ----------------------------------------------------------------------------
// Scratch (device globals)
// ----------------------------------------------------------------------------
__device__ __align__(16) float g_P1[(size_t)AMAX * RP];
__device__ __align__(16) float g_P3[(size_t)AMAX * RP];
__device__ __align__(16) float g_Q2[(size_t)AMAX * RP];
__device__ __align__(16) float g_gate[(size_t)AMAX * FD];
__device__ __align__(16) float g_up[(size_t)AMAX * FD];
__device__ __align__(16) float g_U1p[(size_t)NE * FD * RP];
__device__ __align__(16) float g_U3p[(size_t)NE * FD * RP];
__device__ __align__(16) float g_U2p[(size_t)NE * HD * RP];

__device__ int   g_counts[NE];
__device__ int   g_offsets[NE + 1];
__device__ int   g_cursor[NE];
__device__ int   g_tok[AMAX];
__device__ float g_w[AMAX];
__device__ int   g_sel[TMAX * 2];
__device__ float g_wt[TMAX * 2];

// ----------------------------------------------------------------------------
// helpers
// ----------------------------------------------------------------------------
__device__ __forceinline__ float cvt_tf32(float x) {
    uint32_t u;
    asm("cvt.rna.tf32.f32 %0, %1;" : "=r"(u) : "f"(x));
    return __uint_as_float(u);
}
__device__ __forceinline__ float4 cvt_tf32_4(float4 v) {
    v.x = cvt_tf32(v.x); v.y = cvt_tf32(v.y);
    v.z = cvt_tf32(v.z); v.w = cvt_tf32(v.w);
    return v;
}

// ----------------------------------------------------------------------------
// small kernels
// ----------------------------------------------------------------------------
__global__ void zero_kernel(float* __restrict__ out, size_t n) {
    size_t i = (size_t)blockIdx.x * blockDim.x + threadIdx.x;
    size_t stride = (size_t)gridDim.x * blockDim.x;
    for (; i < n; i += stride) out[i] = 0.0f;
    if (blockIdx.x == 0 && threadIdx.x < NE) {
        g_counts[threadIdx.x] = 0;
        g_cursor[threadIdx.x] = 0;
    }
}

__global__ void router_kernel(const float* __restrict__ x,
                              const float* __restrict__ gw,
                              float* __restrict__ logits_out) {
    int t = blockIdx.x;
    __shared__ float xs[HD];
    __shared__ float lg[NE];
    int tid = threadIdx.x;
    for (int i = tid; i < HD; i += 256) xs[i] = x[(size_t)t * HD + i];
    __syncthreads();
    int w = tid >> 5, lane = tid & 31;
    if (w < NE) {
        const float* grow = gw + (size_t)w * HD;
        float s = 0.0f;
        for (int k = lane; k < HD; k += 32) s += xs[k] * grow[k];
        #pragma unroll
        for (int o = 16; o > 0; o >>= 1) s += __shfl_xor_sync(0xffffffffu, s, o);
        if (lane == 0) lg[w] = s;
    }
    __syncthreads();
    if (tid == 0) {
        float l[NE], m = -1e30f;
        #pragma unroll
        for (int e = 0; e < NE; e++) {
            l[e] = lg[e];
            logits_out[(size_t)t * NE + e] = l[e];
            if (l[e] > m) m = l[e];
        }
        float p[NE];
        #pragma unroll
        for (int e = 0; e < NE; e++) p[e] = expf(l[e] - m);
        int i0 = 0;
        #pragma unroll
        for (int e = 1; e < NE; e++) if (p[e] > p[i0]) i0 = e;
        int i1 = (i0 == 0) ? 1 : 0;
        #pragma unroll
        for (int e = 0; e < NE; e++) {
            if (e == i0) continue;
            if (p[e] > p[i1]) i1 = e;
        }
        float p0 = p[i0], p1 = p[i1];
        float inv = 1.0f / (p0 + p1);
        g_sel[t * 2 + 0] = i0;  g_wt[t * 2 + 0] = p0 * inv;
        g_sel[t * 2 + 1] = i1;  g_wt[t * 2 + 1] = p1 * inv;
        atomicAdd(&g_counts[i0], 1);
        atomicAdd(&g_counts[i1], 1);
    }
}

__global__ void scan_kernel() {
    int off = 0;
    g_offsets[0] = 0;
    for (int e = 0; e < NE; e++) {
        off += g_counts[e];
        g_offsets[e + 1] = off;
        g_cursor[e] = g_offsets[e];
    }
}

__global__ void scatter_kernel(int T) {
    int t = blockIdx.x * blockDim.x + threadIdx.x;
    if (t >= T) return;
    #pragma unroll
    for (int j = 0; j < 2; j++) {
        int e = g_sel[t * 2 + j];
        int slot = atomicAdd(&g_cursor[e], 1);
        g_tok[slot] = t;
        g_w[slot] = g_wt[t * 2 + j];
    }
}

// rows of RD -> rows of RP, zero-padded (fp32 exact)
__global__ void pad_kernel(const float* __restrict__ src, float* __restrict__ dst, int rows) {
    long i = (long)blockIdx.x * blockDim.x + threadIdx.x;
    long total = (long)rows * RP;
    long stride = (long)gridDim.x * blockDim.x;
    for (; i < total; i += stride) {
        int r = (int)(i / RP), c = (int)(i % RP);
        dst[i] = (c < RD) ? src[(long)r * RD + c] : 0.0f;
    }
}

__global__ void silu_mul_kernel(float* __restrict__ g, const float* __restrict__ u, size_t n) {
    size_t i = (size_t)blockIdx.x * blockDim.x + threadIdx.x;
    size_t stride = (size_t)gridDim.x * blockDim.x;
    for (; i < n; i += stride) {
        float gv = g[i];
        float s = 1.0f / (1.0f + expf(-gv));
        g[i] = gv * s * u[i];
    }
}

// ----------------------------------------------------------------------------
// TF32 mma.sync MoE GEMM — exact R2 loop structure (single static smem buffer,
// two syncs per k-tile, register-staged guarded LDG.128, cvt at STS) with
// uniform chained K segments instead of the ragged scalar tail:
//   segment 1: NKT1 = K1/32 tiles from (A1 row-stride K1, B1 row-stride K1)
//   segment 2: NKT2 = K2/32 tiles from (A2 row-stride RP, B2 row-stride RP)
//   C[m,n] = sum_seg1 + sum_seg2   (U zero-pad cols kill P/Q pad junk)
//   EPI 0: crow[n] = (n<NReal ? acc : 0)  (writes all BN cols)
//   EPI 3: atomicAdd(out[tok*HD+n], w[ga]*acc)
// ----------------------------------------------------------------------------
template <int BN, int WARPS_M, int WARPS_N, int K1, int K2, bool GATHER, int EPI>
__global__ __launch_bounds__(256, 1)
void gemm_tf(const float* __restrict__ A1, const float* __restrict__ A2,
             const float* __restrict__ B1base, size_t bs1,
             const float* __restrict__ B2base, size_t bs2,
             float* __restrict__ C, int ldc, int NReal,
             float* __restrict__ outp) {
    constexpr int BM = 128;
    constexpr int BK = 32;
    constexpr int NKT1 = K1 / BK;
    constexpr int NKT2 = K2 / BK;
    constexpr int NKT = NKT1 + NKT2;
    constexpr int WM = BM / WARPS_M;
    constexpr int WN = BN / WARPS_N;
    constexpr int MT = WM / 16;
    constexpr int NTL = WN / 8;
    constexpr int LDA = BK + 4;                 // 36: conflict-free pad
    constexpr int LA = BM * 8 / 256;            // 4 float4/thread (A)
    constexpr int LB = BN * 8 / 256;            // 3 or 4 (B), exact
    static_assert(BM * 8 % 256 == 0 && BN * 8 % 256 == 0, "tiles");
    static_assert(K1 % BK == 0 && K2 % BK == 0, "K");

    const int e = blockIdx.z;
    const int base = g_offsets[e];
    const int cnt = g_offsets[e + 1] - base;
    const int m0 = blockIdx.y * BM;
    if (m0 >= cnt) return;
    const int n0 = blockIdx.x * BN;

    const float* B1 = B1base + (size_t)e * bs1;
    const float* B2 = (K2 > 0) ? (B2base + (size_t)e * bs2) : nullptr;

    __shared__ float As[BM][LDA];
    __shared__ float Bs[BN][LDA];

    const int tid = threadIdx.x;
    const int lane = tid & 31;
    const int wid = tid >> 5;
    const int wm = wid % WARPS_M;
    const int wn = wid / WARPS_M;

    // ---- per-thread load metadata (fixed across k-tiles) ----
    const float* aptr1[LA];
    const float* aptr2[LA];
    int arow[LA], akq[LA];
    bool aok[LA];
    #pragma unroll
    for (int i = 0; i < LA; i++) {
        int idx = tid + i * 256;
        arow[i] = idx >> 3;
        akq[i] = (idx & 7) * 4;
        int m = m0 + arow[i];
        aok[i] = (m < cnt);
        int ga = base + (aok[i] ? m : 0);
        long r1 = GATHER ? (long)g_tok[ga] : (long)ga;
        aptr1[i] = A1 + r1 * K1 + akq[i];
        aptr2[i] = (K2 > 0) ? (A2 + (long)ga * RP + akq[i]) : nullptr;
    }
    const float* bptr1[LB];
    const float* bptr2[LB];
    int brow[LB], bkq[LB];
    bool bok[LB];
    #pragma unroll
    for (int i = 0; i < LB; i++) {
        int idx = tid + i * 256;
        brow[i] = idx >> 3;
        bkq[i] = (idx & 7) * 4;
        int n = n0 + brow[i];
        bok[i] = (n < NReal);
        int nn = bok[i] ? n : 0;
        bptr1[i] = B1 + (size_t)nn * K1 + bkq[i];
        bptr2[i] = (K2 > 0) ? (B2 + (size_t)nn * RP + bkq[i]) : nullptr;
    }

    float4 ra[LA], rb[LB];
    auto load_tiles = [&](int kt) {
        if (K2 == 0 || kt < NKT1) {
            const int kb = kt * BK;
            #pragma unroll
            for (int i = 0; i < LA; i++)
                ra[i] = aok[i] ? *reinterpret_cast<const float4*>(aptr1[i] + kb)
                               : make_float4(0.f, 0.f, 0.f, 0.f);
            #pragma unroll
            for (int i = 0; i < LB; i++)
                rb[i] = bok[i] ? *reinterpret_cast<const float4*>(bptr1[i] + kb)
                               : make_float4(0.f, 0.f, 0.f, 0.f);
        } else {
            const int kb = (kt - NKT1) * BK;
            #pragma unroll
            for (int i = 0; i < LA; i++)
                ra[i] = aok[i] ? *reinterpret_cast<const float4*>(aptr2[i] + kb)
                               : make_float4(0.f, 0.f, 0.f, 0.f);
            #pragma unroll
            for (int i = 0; i < LB; i++)
                rb[i] = bok[i] ? *reinterpret_cast<const float4*>(bptr2[i] + kb)
                               : make_float4(0.f, 0.f, 0.f, 0.f);
        }
    };
    auto store_tiles = [&]() {
        #pragma unroll
        for (int i = 0; i < LA; i++)
            *reinterpret_cast<float4*>(&As[arow[i]][akq[i]]) = cvt_tf32_4(ra[i]);
        #pragma unroll
        for (int i = 0; i < LB; i++)
            *reinterpret_cast<float4*>(&Bs[brow[i]][bkq[i]]) = cvt_tf32_4(rb[i]);
    };

    float acc[MT][NTL][4];
    #pragma unroll
    for (int mt = 0; mt < MT; mt++)
        #pragma unroll
        for (int nt = 0; nt < NTL; nt++)
            #pragma unroll
            for (int j = 0; j < 4; j++) acc[mt][nt][j] = 0.f;

    load_tiles(0);
    store_tiles();
    __syncthreads();

    for (int kt = 0; kt < NKT; kt++) {
        if (kt + 1 < NKT) load_tiles(kt + 1);   // overlap with mma below
        #pragma unroll
        for (int ks = 0; ks < BK / 8; ks++) {
            const int k0 = ks * 8 + (lane & 3);
            uint32_t afr[MT][4];
            uint32_t bfr[NTL][2];
            #pragma unroll
            for (int mt = 0; mt < MT; mt++) {
                int m = wm * WM + mt * 16 + (lane >> 2);
                afr[mt][0] = __float_as_uint(As[m][k0]);
                afr[mt][1] = __float_as_uint(As[m + 8][k0]);
                afr[mt][2] = __float_as_uint(As[m][k0 + 4]);
                afr[mt][3] = __float_as_uint(As[m + 8][k0 + 4]);
            }
            #pragma unroll
            for (int nt = 0; nt < NTL; nt++) {
                int n = wn * WN + nt * 8 + (lane >> 2);
                bfr[nt][0] = __float_as_uint(Bs[n][k0]);
                bfr[nt][1] = __float_as_uint(Bs[n][k0 + 4]);
            }
            #pragma unroll
            for (int mt = 0; mt < MT; mt++)
                #pragma unroll
                for (int nt = 0; nt < NTL; nt++) {
                    asm volatile(
                        "mma.sync.aligned.m16n8k8.row.col.f32.tf32.tf32.f32 "
                        "{%0,%1,%2,%3}, {%4,%5,%6,%7}, {%8,%9}, {%0,%1,%2,%3};\n"
                        : "+f"(acc[mt][nt][0]), "+f"(acc[mt][nt][1]),
                          "+f"(acc[mt][nt][2]), "+f"(acc[mt][nt][3])
                        : "r"(afr[mt][0]), "r"(afr[mt][1]),
                          "r"(afr[mt][2]), "r"(afr[mt][3]),
                          "r"(bfr[nt][0]), "r"(bfr[nt][1]));
                }
        }
        if (kt + 1 < NKT) {
            __syncthreads();
            store_tiles();
            __syncthreads();
        }
    }

    // ---- epilogue ----
    #pragma unroll
    for (int mt = 0; mt < MT; mt++) {
        #pragma unroll
        for (int h = 0; h < 2; h++) {
            int ml = wm * WM + mt * 16 + (lane >> 2) + h * 8;
            int m = m0 + ml;
            if (m >= cnt) continue;
            int ga = base + m;
            if (EPI == 0) {
                float* crow = C + (size_t)ga * ldc;
                #pragma unroll
                for (int nt = 0; nt < NTL; nt++) {
                    int col = n0 + wn * WN + nt * 8 + 2 * (lane & 3);
                    float2 v;
                    v.x = (col < NReal) ? acc[mt][nt][h * 2 + 0] : 0.0f;
                    v.y = (col + 1 < NReal) ? acc[mt][nt][h * 2 + 1] : 0.0f;
                    *reinterpret_cast<float2*>(crow + col) = v;
                }
            } else {
                int tok = g_tok[ga];
                float wgt = g_w[ga];
                float* orow = outp + (size_t)tok * HD;
                #pragma unroll
                for (int nt = 0; nt < NTL; nt++) {
                    int col = n0 + wn * WN + nt * 8 + 2 * (lane & 3);
                    atomicAdd(&orow[col], wgt * acc[mt][nt][h * 2 + 0]);
                    atomicAdd(&orow[col + 1], wgt * acc[mt][nt][h * 2 + 1]);
                }
            }
        }
    }
}

// ----------------------------------------------------------------------------
// kernel_launch
// Inputs: hidden_states, gate_w, W1, W2, W3, U1, V1, U2, V2, U3, V3
// Output: [out (T*H f32)] then [router_logits (T*E f32)]
// ----------------------------------------------------------------------------
extern "C" void kernel_launch(void* const* d_in, const int* in_sizes, int n_in,
                              void* d_out, int out_size) {
    const float* x  = (const float*)d_in[0];
    const float* gw = (const float*)d_in[1];
    const float* W1 = (const float*)d_in[2];
    const float* W2 = (const float*)d_in[3];
    const float* W3 = (const float*)d_in[4];
    const float* U1 = (const float*)d_in[5];
    const float* V1 = (const float*)d_in[6];
    const float* U2 = (const float*)d_in[7];
    const float* V2 = (const float*)d_in[8];
    const float* U3 = (const float*)d_in[9];
    const float* V3 = (const float*)d_in[10];
    (void)n_in; (void)out_size;

    const int T = in_sizes[0] / HD;
    const int A = T * 2;

    float* out    = (float*)d_out;
    float* logits = out + (size_t)T * HD;

    zero_kernel<<<2048, 256>>>(out, (size_t)T * HD);
    router_kernel<<<T, 256>>>(x, gw, logits);
    scan_kernel<<<1, 1>>>();
    scatter_kernel<<<(T + 255) / 256, 256>>>(T);

    // zero-padded low-rank U matrices (fp32, exact)
    pad_kernel<<<2048, 256>>>(U1, g_U1p, NE * FD);
    pad_kernel<<<2048, 256>>>(U3, g_U3p, NE * FD);
    pad_kernel<<<1024, 256>>>(U2, g_U2p, NE * HD);

    const int mt128 = (T + 127) / 128;

    // P1 = X@V1^T, P3 = X@V3^T  (K=1024; N=79 -> stride 96, pad cols zero-written)
    {
        dim3 grid(1, mt128, NE);
        gemm_tf<96, 4, 2, HD, 0, true, 0><<<grid, 256>>>(
            x, nullptr, V1, (size_t)RD * HD, nullptr, 0, g_P1, RP, RD, nullptr);
        gemm_tf<96, 4, 2, HD, 0, true, 0><<<grid, 256>>>(
            x, nullptr, V3, (size_t)RD * HD, nullptr, 0, g_P3, RP, RD, nullptr);
    }
    // gate = X@W1^T + P1@U1p^T, up = X@W3^T + P3@U3p^T  (chained 32+3 tiles)
    {
        dim3 grid(FD / 128, mt128, NE);
        gemm_tf<128, 2, 4, HD, RP, true, 0><<<grid, 256>>>(
            x, g_P1, W1, (size_t)FD * HD, g_U1p, (size_t)FD * RP, g_gate, FD, FD, nullptr);
        gemm_tf<128, 2, 4, HD, RP, true, 0><<<grid, 256>>>(
            x, g_P3, W3, (size_t)FD * HD, g_U3p, (size_t)FD * RP, g_up, FD, FD, nullptr);
    }
    // Hact = silu(gate)*up
    silu_mul_kernel<<<4096, 256>>>(g_gate, g_up, (size_t)A * FD);

    // Q2 = Hact@V2^T  (K=3584; N=79 -> stride 96, pad cols zero-written)
    {
        dim3 grid(1, mt128, NE);
        gemm_tf<96, 4, 2, FD, 0, false, 0><<<grid, 256>>>(
            g_gate, nullptr, V2, (size_t)RD * FD, nullptr, 0, g_Q2, RP, RD, nullptr);
    }
    // out += w*(Hact@W2^T + Q2@U2p^T)  (chained 112+3 tiles, atomic scatter)
    {
        dim3 grid(HD / 128, mt128, NE);
        gemm_tf<128, 2, 4, FD, RP, false, 3><<<grid, 256>>>(
            g_gate, g_Q2, W2, (size_t)HD * FD, g_U2p, (size_t)HD * RP, nullptr, HD, HD, out);
    }
}